// round 1
// baseline (speedup 1.0000x reference)
#include <cuda_runtime.h>
#include <cuda_bf16.h>
#include <math.h>

// ---------------- model dims ----------------
#define B_ 4
#define L_ 1024
#define D_IN 128
#define D_MODEL 512
#define N_LAYERS 2
#define N_CLASSES 3
#define D_INNER 1024          // 2*D_MODEL
#define D_STATE 64
#define D_CONV 2
#define DT_RANK 32
#define ML (B_ * L_)          // 4096 rows

// ---------------- scratch (device globals; no allocation) ----------------
__device__ float g_h[ML * D_MODEL];          // 2M
__device__ float g_xz[ML * 2 * D_INNER];     // 8M (xc = [:,0:1024], z = [:,1024:2048])
__device__ float g_xc[ML * D_INNER];         // 4M (conv+silu output)
__device__ float g_dbc[ML * (DT_RANK + 2 * D_STATE)]; // 4096*160
__device__ float g_dt[ML * D_INNER];         // 4M
__device__ float g_y[ML * D_INNER];          // 4M

// ---------------- generic fp32 GEMM: C = A(M,K; lda) * W(N,K)^T (+bias)(+act) --------
// BM=BN=128, BK=8, 256 threads, 8x8 per thread.
#define BM 128
#define BN 128
#define BK 8
#define TM 8
#define TN 8

__device__ __forceinline__ float softplus_f(float v) {
    return (v > 20.f) ? v : log1pf(__expf(v));
}

__global__ __launch_bounds__(256, 2)
void gemm_kernel(const float* __restrict__ A, const float* __restrict__ W,
                 const float* __restrict__ bias, float* __restrict__ C,
                 int M, int N, int K, int lda, int act)
{
    __shared__ float As[BK][BM];
    __shared__ float Ws[BK][BN];

    const int tid = threadIdx.x;
    const int m0 = blockIdx.y * BM;
    const int n0 = blockIdx.x * BN;

    const int loadRow = tid >> 1;          // 0..127
    const int loadCol = (tid & 1) * 4;     // 0 or 4

    const int threadRow = (tid >> 4) * TM; // 0..120 step 8
    const int threadCol = (tid & 15) * TN;

    float acc[TM][TN];
#pragma unroll
    for (int i = 0; i < TM; i++)
#pragma unroll
        for (int j = 0; j < TN; j++) acc[i][j] = 0.f;

    const float* Ap = A + (long)(m0 + loadRow) * lda + loadCol;
    const bool wValid = (n0 + loadRow) < N;
    const float* Wp = W + (long)(n0 + loadRow) * K + loadCol;

    for (int k0 = 0; k0 < K; k0 += BK) {
        // load A tile (M rows always valid: M % 128 == 0)
        float4 av = *(const float4*)(Ap + k0);
        As[loadCol + 0][loadRow] = av.x;
        As[loadCol + 1][loadRow] = av.y;
        As[loadCol + 2][loadRow] = av.z;
        As[loadCol + 3][loadRow] = av.w;
        // load W tile (guard N)
        float4 wv = make_float4(0.f, 0.f, 0.f, 0.f);
        if (wValid) wv = *(const float4*)(Wp + k0);
        Ws[loadCol + 0][loadRow] = wv.x;
        Ws[loadCol + 1][loadRow] = wv.y;
        Ws[loadCol + 2][loadRow] = wv.z;
        Ws[loadCol + 3][loadRow] = wv.w;
        __syncthreads();

#pragma unroll
        for (int k = 0; k < BK; k++) {
            float regM[TM], regN[TN];
            *(float4*)&regM[0] = *(const float4*)&As[k][threadRow];
            *(float4*)&regM[4] = *(const float4*)&As[k][threadRow + 4];
            *(float4*)&regN[0] = *(const float4*)&Ws[k][threadCol];
            *(float4*)&regN[4] = *(const float4*)&Ws[k][threadCol + 4];
#pragma unroll
            for (int i = 0; i < TM; i++)
#pragma unroll
                for (int j = 0; j < TN; j++)
                    acc[i][j] = fmaf(regM[i], regN[j], acc[i][j]);
        }
        __syncthreads();
    }

#pragma unroll
    for (int i = 0; i < TM; i++) {
        const int m = m0 + threadRow + i;
        float* Crow = C + (long)m * N;
#pragma unroll
        for (int j = 0; j < TN; j++) {
            const int n = n0 + threadCol + j;
            if (n < N) {
                float v = acc[i][j];
                if (bias) v += bias[n];
                if (act == 1) v = softplus_f(v);
                Crow[n] = v;
            }
        }
    }
}

// ---------------- conv (D_CONV=2) + silu ----------------
__global__ void conv_silu_kernel(const float* __restrict__ xz,
                                 const float* __restrict__ cw,
                                 const float* __restrict__ cb,
                                 float* __restrict__ xc)
{
    int idx = blockIdx.x * blockDim.x + threadIdx.x;  // over ML * D_INNER = 4M
    if (idx >= ML * D_INNER) return;
    int d = idx & (D_INNER - 1);
    int row = idx >> 10;            // b*L + t
    int t = row & (L_ - 1);
    float cur = xz[(long)row * (2 * D_INNER) + d];
    float prev = (t > 0) ? xz[(long)(row - 1) * (2 * D_INNER) + d] : 0.f;
    float v = prev * cw[d * 2 + 0] + cur * cw[d * 2 + 1] + cb[d];
    xc[idx] = v / (1.f + __expf(-v));  // silu
}

// ---------------- selective scan: one warp per (b, d), 2 states per lane ----------
__global__ __launch_bounds__(128)
void scan_kernel(const float* __restrict__ dt, const float* __restrict__ xc,
                 const float* __restrict__ dbc, const float* __restrict__ xz,
                 const float* __restrict__ A_log, const float* __restrict__ Dp,
                 float* __restrict__ y)
{
    const int gw = (blockIdx.x * blockDim.x + threadIdx.x) >> 5;
    const int lane = threadIdx.x & 31;
    const int b = gw >> 10;
    const int d = gw & (D_INNER - 1);

    const float A0 = -__expf(A_log[d * D_STATE + 2 * lane]);
    const float A1 = -__expf(A_log[d * D_STATE + 2 * lane + 1]);
    const float Dd = Dp[d];

    const float* dtp = dt + (long)b * L_ * D_INNER + d;
    const float* xp  = xc + (long)b * L_ * D_INNER + d;
    const float* bcp = dbc + (long)b * L_ * 160 + DT_RANK + 2 * lane; // B; C at +64
    const float* zp  = xz + (long)b * L_ * (2 * D_INNER) + D_INNER + d;
    float* yp        = y  + (long)b * L_ * D_INNER + d;

    float h0 = 0.f, h1 = 0.f;
    for (int t = 0; t < L_; t++) {
        const float dtv = dtp[t * D_INNER];
        const float xv  = xp[t * D_INNER];
        const float2 Bv = *(const float2*)(bcp + t * 160);
        const float2 Cv = *(const float2*)(bcp + t * 160 + D_STATE);
        const float u = dtv * xv;
        h0 = h0 * __expf(dtv * A0) + u * Bv.x;
        h1 = h1 * __expf(dtv * A1) + u * Bv.y;
        float p = h0 * Cv.x + h1 * Cv.y;
#pragma unroll
        for (int o = 16; o; o >>= 1) p += __shfl_xor_sync(0xffffffffu, p, o);
        if (lane == 0) {
            const float zv = zp[t * (2 * D_INNER)];
            const float yv = p + xv * Dd;
            yp[t * D_INNER] = yv * (zv / (1.f + __expf(-zv)));
        }
    }
}

// ---------------- final FC: out[b,c] = h[b,L-1,:] . fc_w[c,:] + fc_b[c] ----------
__global__ void fc_kernel(const float* __restrict__ h, const float* __restrict__ fc_w,
                          const float* __restrict__ fc_b, float* __restrict__ out)
{
    const int w = threadIdx.x >> 5;       // 12 warps
    const int lane = threadIdx.x & 31;
    if (w >= B_ * N_CLASSES) return;
    const int b = w / N_CLASSES, c = w % N_CLASSES;
    const float* hp = h + (long)(b * L_ + (L_ - 1)) * D_MODEL;
    float s = 0.f;
    for (int k = lane; k < D_MODEL; k += 32) s += hp[k] * fc_w[c * D_MODEL + k];
#pragma unroll
    for (int o = 16; o; o >>= 1) s += __shfl_xor_sync(0xffffffffu, s, o);
    if (lane == 0) out[b * N_CLASSES + c] = s + fc_b[c];
}

// ---------------- launch ----------------
extern "C" void kernel_launch(void* const* d_in, const int* in_sizes, int n_in,
                              void* d_out, int out_size)
{
    const float* x        = (const float*)d_in[0];
    const float* exp_w    = (const float*)d_in[1];
    const float* exp_b    = (const float*)d_in[2];
    const float* in_w     = (const float*)d_in[3];
    const float* conv_w   = (const float*)d_in[4];
    const float* conv_b   = (const float*)d_in[5];
    const float* xproj_w  = (const float*)d_in[6];
    const float* dtproj_w = (const float*)d_in[7];
    const float* dtproj_b = (const float*)d_in[8];
    const float* A_log    = (const float*)d_in[9];
    const float* Dp       = (const float*)d_in[10];
    const float* out_w    = (const float*)d_in[11];
    const float* fc_w     = (const float*)d_in[12];
    const float* fc_b     = (const float*)d_in[13];
    float* out = (float*)d_out;

    float *ph, *pxz, *pxc, *pdbc, *pdt, *py;
    cudaGetSymbolAddress((void**)&ph,   g_h);
    cudaGetSymbolAddress((void**)&pxz,  g_xz);
    cudaGetSymbolAddress((void**)&pxc,  g_xc);
    cudaGetSymbolAddress((void**)&pdbc, g_dbc);
    cudaGetSymbolAddress((void**)&pdt,  g_dt);
    cudaGetSymbolAddress((void**)&py,   g_y);

    // embed: h = x @ exp_w^T + exp_b   (M=4096, N=512, K=128)
    gemm_kernel<<<dim3(D_MODEL / BN, ML / BM), 256>>>(x, exp_w, exp_b, ph,
                                                      ML, D_MODEL, D_IN, D_IN, 0);

    for (int l = 0; l < N_LAYERS; l++) {
        const float* in_w_l   = in_w     + (long)l * 2 * D_INNER * D_MODEL;
        const float* conv_w_l = conv_w   + (long)l * D_INNER * D_CONV;
        const float* conv_b_l = conv_b   + (long)l * D_INNER;
        const float* xproj_l  = xproj_w  + (long)l * 160 * D_INNER;
        const float* dtw_l    = dtproj_w + (long)l * D_INNER * DT_RANK;
        const float* dtb_l    = dtproj_b + (long)l * D_INNER;
        const float* Alog_l   = A_log    + (long)l * D_INNER * D_STATE;
        const float* Dp_l     = Dp       + (long)l * D_INNER;
        const float* out_w_l  = out_w    + (long)l * D_MODEL * D_INNER;

        // xz = h @ in_w^T   (4096 x 2048, K=512)
        gemm_kernel<<<dim3(2 * D_INNER / BN, ML / BM), 256>>>(ph, in_w_l, nullptr, pxz,
                                                              ML, 2 * D_INNER, D_MODEL, D_MODEL, 0);
        // conv + silu over xc half
        conv_silu_kernel<<<(ML * D_INNER + 255) / 256, 256>>>(pxz, conv_w_l, conv_b_l, pxc);
        // dbc = xc @ xproj^T  (4096 x 160, K=1024)
        gemm_kernel<<<dim3((160 + BN - 1) / BN, ML / BM), 256>>>(pxc, xproj_l, nullptr, pdbc,
                                                                 ML, 160, D_INNER, D_INNER, 0);
        // dt = softplus(dbc[:, :32] @ dtproj^T + b)  (4096 x 1024, K=32, lda=160)
        gemm_kernel<<<dim3(D_INNER / BN, ML / BM), 256>>>(pdbc, dtw_l, dtb_l, pdt,
                                                          ML, D_INNER, DT_RANK, 160, 1);
        // selective scan + Dp skip + silu(z) gating -> y
        scan_kernel<<<(B_ * D_INNER) / 4, 128>>>(pdt, pxc, pdbc, pxz, Alog_l, Dp_l, py);
        // h = y @ out_w^T  (4096 x 512, K=1024)
        gemm_kernel<<<dim3(D_MODEL / BN, ML / BM), 256>>>(py, out_w_l, nullptr, ph,
                                                          ML, D_MODEL, D_INNER, D_INNER, 0);
    }

    fc_kernel<<<1, 384>>>(ph, fc_w, fc_b, out);
}

// round 2
// speedup vs baseline: 1.1514x; 1.1514x over previous
#include <cuda_runtime.h>
#include <cuda_bf16.h>
#include <math.h>

// ---------------- model dims ----------------
#define B_ 4
#define L_ 1024
#define D_IN 128
#define D_MODEL 512
#define N_LAYERS 2
#define N_CLASSES 3
#define D_INNER 1024          // 2*D_MODEL
#define D_STATE 64
#define D_CONV 2
#define DT_RANK 32
#define ML (B_ * L_)          // 4096 rows

// ---------------- scratch (device globals; no allocation) ----------------
__device__ float g_h[ML * D_MODEL];
__device__ float g_xz[ML * 2 * D_INNER];     // xc = [:,0:1024], z = [:,1024:2048]
__device__ float g_xc[ML * D_INNER];
__device__ float g_dbc[ML * (DT_RANK + 2 * D_STATE)];
__device__ float g_dt[ML * D_INNER];
__device__ float g_y[ML * D_INNER];

__device__ __forceinline__ float softplus_f(float v) {
    return (v > 20.f) ? v : log1pf(__expf(v));
}
__device__ __forceinline__ float to_tf32(float x) {
    float r; asm("cvt.rna.tf32.f32 %0, %1;" : "=f"(r) : "f"(x)); return r;
}
__device__ __forceinline__ void mma_tf32(float* c, const float4& a, const float2& b) {
    asm volatile(
        "mma.sync.aligned.m16n8k8.row.col.f32.tf32.tf32.f32 "
        "{%0,%1,%2,%3}, {%4,%5,%6,%7}, {%8,%9}, {%0,%1,%2,%3};\n"
        : "+f"(c[0]), "+f"(c[1]), "+f"(c[2]), "+f"(c[3])
        : "r"(__float_as_uint(a.x)), "r"(__float_as_uint(a.y)),
          "r"(__float_as_uint(a.z)), "r"(__float_as_uint(a.w)),
          "r"(__float_as_uint(b.x)), "r"(__float_as_uint(b.y)));
}

// ---------------- 3xTF32 tensor-core GEMM: C = A(M,K;lda) @ W(N,K)^T (+bias)(+act)
// CTA tile 128x64, BK=16, 128 threads = 4 warps of 64x32.
// SMEM strides: 136 and 72 (== 8 mod 32) => conflict-free fragment LDS.
#define SA 136
#define SW 72

__global__ __launch_bounds__(128)
void gemm3t(const float* __restrict__ A, const float* __restrict__ W,
            const float* __restrict__ bias, float* __restrict__ C,
            int M, int N, int K, int lda, int act)
{
    __shared__ float As_hi[16][SA], As_lo[16][SA];
    __shared__ float Ws_hi[16][SW], Ws_lo[16][SW];

    const int t = threadIdx.x;
    const int lane = t & 31, w = t >> 5;
    const int l4 = lane & 3, g = lane >> 2;
    const int wm = (w & 1) * 64, wn = (w >> 1) * 32;
    const int m0 = blockIdx.y * 128, n0 = blockIdx.x * 64;

    const int wr = t & 63, wk = (t >> 6) * 8;
    const bool wvalid = (n0 + wr) < N;

    float acc[4][4][4];
#pragma unroll
    for (int i = 0; i < 4; i++)
#pragma unroll
        for (int j = 0; j < 4; j++)
#pragma unroll
            for (int e = 0; e < 4; e++) acc[i][j][e] = 0.f;

    const float* Arow = A + (long)(m0 + t) * lda;
    const float* Wrow = W + (long)(n0 + wr) * K + wk;

    for (int k0 = 0; k0 < K; k0 += 16) {
        // stage A tile 128x16, split hi/lo
#pragma unroll
        for (int q = 0; q < 4; q++) {
            float4 v = *(const float4*)(Arow + k0 + q * 4);
            float h;
            h = to_tf32(v.x); As_hi[q*4+0][t] = h; As_lo[q*4+0][t] = v.x - h;
            h = to_tf32(v.y); As_hi[q*4+1][t] = h; As_lo[q*4+1][t] = v.y - h;
            h = to_tf32(v.z); As_hi[q*4+2][t] = h; As_lo[q*4+2][t] = v.z - h;
            h = to_tf32(v.w); As_hi[q*4+3][t] = h; As_lo[q*4+3][t] = v.w - h;
        }
        // stage W tile 64x16, split hi/lo
#pragma unroll
        for (int q = 0; q < 2; q++) {
            float4 v = wvalid ? *(const float4*)(Wrow + k0 + q * 4)
                              : make_float4(0.f, 0.f, 0.f, 0.f);
            int kk = wk + q * 4;
            float h;
            h = to_tf32(v.x); Ws_hi[kk+0][wr] = h; Ws_lo[kk+0][wr] = v.x - h;
            h = to_tf32(v.y); Ws_hi[kk+1][wr] = h; Ws_lo[kk+1][wr] = v.y - h;
            h = to_tf32(v.z); Ws_hi[kk+2][wr] = h; Ws_lo[kk+2][wr] = v.z - h;
            h = to_tf32(v.w); Ws_hi[kk+3][wr] = h; Ws_lo[kk+3][wr] = v.w - h;
        }
        __syncthreads();

#pragma unroll
        for (int ks = 0; ks < 2; ks++) {
            const int r0 = ks * 8 + l4, r1 = r0 + 4;
            float4 a[4];
            float2 bh[4], bl[4];
#pragma unroll
            for (int j = 0; j < 4; j++) {
                bh[j].x = Ws_hi[r0][wn + 8*j + g];
                bh[j].y = Ws_hi[r1][wn + 8*j + g];
            }
#pragma unroll
            for (int i = 0; i < 4; i++) {
                a[i].x = As_hi[r0][wm + 16*i + g];
                a[i].y = As_hi[r0][wm + 16*i + g + 8];
                a[i].z = As_hi[r1][wm + 16*i + g];
                a[i].w = As_hi[r1][wm + 16*i + g + 8];
            }
#pragma unroll
            for (int i = 0; i < 4; i++)
#pragma unroll
                for (int j = 0; j < 4; j++) mma_tf32(acc[i][j], a[i], bh[j]);
            // hi * lo
#pragma unroll
            for (int j = 0; j < 4; j++) {
                bl[j].x = Ws_lo[r0][wn + 8*j + g];
                bl[j].y = Ws_lo[r1][wn + 8*j + g];
            }
#pragma unroll
            for (int i = 0; i < 4; i++)
#pragma unroll
                for (int j = 0; j < 4; j++) mma_tf32(acc[i][j], a[i], bl[j]);
            // lo * hi
#pragma unroll
            for (int i = 0; i < 4; i++) {
                a[i].x = As_lo[r0][wm + 16*i + g];
                a[i].y = As_lo[r0][wm + 16*i + g + 8];
                a[i].z = As_lo[r1][wm + 16*i + g];
                a[i].w = As_lo[r1][wm + 16*i + g + 8];
            }
#pragma unroll
            for (int i = 0; i < 4; i++)
#pragma unroll
                for (int j = 0; j < 4; j++) mma_tf32(acc[i][j], a[i], bh[j]);
        }
        __syncthreads();
    }

    // epilogue
#pragma unroll
    for (int i = 0; i < 4; i++) {
        const int mr0 = m0 + wm + 16*i + g;
        const int mr1 = mr0 + 8;
#pragma unroll
        for (int j = 0; j < 4; j++) {
            const int n = n0 + wn + 8*j + 2*l4;
            if (n < N) {
                float b0 = 0.f, b1 = 0.f;
                if (bias) { b0 = bias[n]; b1 = bias[n + 1]; }
                float v0 = acc[i][j][0] + b0, v1 = acc[i][j][1] + b1;
                float v2 = acc[i][j][2] + b0, v3 = acc[i][j][3] + b1;
                if (act == 1) {
                    v0 = softplus_f(v0); v1 = softplus_f(v1);
                    v2 = softplus_f(v2); v3 = softplus_f(v3);
                }
                *(float2*)(C + (long)mr0 * N + n) = make_float2(v0, v1);
                *(float2*)(C + (long)mr1 * N + n) = make_float2(v2, v3);
            }
        }
    }
}

// ---------------- conv (D_CONV=2) + silu ----------------
__global__ void conv_silu_kernel(const float* __restrict__ xz,
                                 const float* __restrict__ cw,
                                 const float* __restrict__ cb,
                                 float* __restrict__ xc)
{
    int idx = blockIdx.x * blockDim.x + threadIdx.x;
    if (idx >= ML * D_INNER) return;
    int d = idx & (D_INNER - 1);
    int row = idx >> 10;
    int tt = row & (L_ - 1);
    float cur = xz[(long)row * (2 * D_INNER) + d];
    float prev = (tt > 0) ? xz[(long)(row - 1) * (2 * D_INNER) + d] : 0.f;
    float v = prev * cw[d * 2 + 0] + cur * cw[d * 2 + 1] + cb[d];
    xc[idx] = v / (1.f + __expf(-v));
}

// ---------------- selective scan: one warp per (b, d), 2 states per lane ----------
__global__ __launch_bounds__(128)
void scan_kernel(const float* __restrict__ dt, const float* __restrict__ xc,
                 const float* __restrict__ dbc, const float* __restrict__ xz,
                 const float* __restrict__ A_log, const float* __restrict__ Dp,
                 float* __restrict__ y)
{
    const int gw = (blockIdx.x * blockDim.x + threadIdx.x) >> 5;
    const int lane = threadIdx.x & 31;
    const int b = gw >> 10;
    const int d = gw & (D_INNER - 1);

    const float A0 = -__expf(A_log[d * D_STATE + 2 * lane]);
    const float A1 = -__expf(A_log[d * D_STATE + 2 * lane + 1]);
    const float Dd = Dp[d];

    const float* dtp = dt + (long)b * L_ * D_INNER + d;
    const float* xp  = xc + (long)b * L_ * D_INNER + d;
    const float* bcp = dbc + (long)b * L_ * 160 + DT_RANK + 2 * lane;
    const float* zp  = xz + (long)b * L_ * (2 * D_INNER) + D_INNER + d;
    float* yp        = y  + (long)b * L_ * D_INNER + d;

    float h0 = 0.f, h1 = 0.f;
    for (int t = 0; t < L_; t++) {
        const float dtv = dtp[t * D_INNER];
        const float xv  = xp[t * D_INNER];
        const float2 Bv = *(const float2*)(bcp + t * 160);
        const float2 Cv = *(const float2*)(bcp + t * 160 + D_STATE);
        const float u = dtv * xv;
        h0 = h0 * __expf(dtv * A0) + u * Bv.x;
        h1 = h1 * __expf(dtv * A1) + u * Bv.y;
        float p = h0 * Cv.x + h1 * Cv.y;
#pragma unroll
        for (int o = 16; o; o >>= 1) p += __shfl_xor_sync(0xffffffffu, p, o);
        if (lane == 0) {
            const float zv = zp[t * (2 * D_INNER)];
            const float yv = p + xv * Dd;
            yp[t * D_INNER] = yv * (zv / (1.f + __expf(-zv)));
        }
    }
}

// ---------------- final FC ----------------
__global__ void fc_kernel(const float* __restrict__ h, const float* __restrict__ fc_w,
                          const float* __restrict__ fc_b, float* __restrict__ out)
{
    const int w = threadIdx.x >> 5;
    const int lane = threadIdx.x & 31;
    if (w >= B_ * N_CLASSES) return;
    const int b = w / N_CLASSES, c = w % N_CLASSES;
    const float* hp = h + (long)(b * L_ + (L_ - 1)) * D_MODEL;
    float s = 0.f;
    for (int k = lane; k < D_MODEL; k += 32) s += hp[k] * fc_w[c * D_MODEL + k];
#pragma unroll
    for (int o = 16; o; o >>= 1) s += __shfl_xor_sync(0xffffffffu, s, o);
    if (lane == 0) out[b * N_CLASSES + c] = s + fc_b[c];
}

// ---------------- launch ----------------
extern "C" void kernel_launch(void* const* d_in, const int* in_sizes, int n_in,
                              void* d_out, int out_size)
{
    const float* x        = (const float*)d_in[0];
    const float* exp_w    = (const float*)d_in[1];
    const float* exp_b    = (const float*)d_in[2];
    const float* in_w     = (const float*)d_in[3];
    const float* conv_w   = (const float*)d_in[4];
    const float* conv_b   = (const float*)d_in[5];
    const float* xproj_w  = (const float*)d_in[6];
    const float* dtproj_w = (const float*)d_in[7];
    const float* dtproj_b = (const float*)d_in[8];
    const float* A_log    = (const float*)d_in[9];
    const float* Dp       = (const float*)d_in[10];
    const float* out_w    = (const float*)d_in[11];
    const float* fc_w     = (const float*)d_in[12];
    const float* fc_b     = (const float*)d_in[13];
    float* out = (float*)d_out;

    float *ph, *pxz, *pxc, *pdbc, *pdt, *py;
    cudaGetSymbolAddress((void**)&ph,   g_h);
    cudaGetSymbolAddress((void**)&pxz,  g_xz);
    cudaGetSymbolAddress((void**)&pxc,  g_xc);
    cudaGetSymbolAddress((void**)&pdbc, g_dbc);
    cudaGetSymbolAddress((void**)&pdt,  g_dt);
    cudaGetSymbolAddress((void**)&py,   g_y);

    // embed: h = x @ exp_w^T + exp_b   (4096 x 512, K=128)
    gemm3t<<<dim3(D_MODEL / 64, ML / 128), 128>>>(x, exp_w, exp_b, ph,
                                                  ML, D_MODEL, D_IN, D_IN, 0);

    for (int l = 0; l < N_LAYERS; l++) {
        const float* in_w_l   = in_w     + (long)l * 2 * D_INNER * D_MODEL;
        const float* conv_w_l = conv_w   + (long)l * D_INNER * D_CONV;
        const float* conv_b_l = conv_b   + (long)l * D_INNER;
        const float* xproj_l  = xproj_w  + (long)l * 160 * D_INNER;
        const float* dtw_l    = dtproj_w + (long)l * D_INNER * DT_RANK;
        const float* dtb_l    = dtproj_b + (long)l * D_INNER;
        const float* Alog_l   = A_log    + (long)l * D_INNER * D_STATE;
        const float* Dp_l     = Dp       + (long)l * D_INNER;
        const float* out_w_l  = out_w    + (long)l * D_MODEL * D_INNER;

        // xz = h @ in_w^T   (4096 x 2048, K=512)
        gemm3t<<<dim3(2 * D_INNER / 64, ML / 128), 128>>>(ph, in_w_l, nullptr, pxz,
                                                          ML, 2 * D_INNER, D_MODEL, D_MODEL, 0);
        // conv + silu
        conv_silu_kernel<<<(ML * D_INNER + 255) / 256, 256>>>(pxz, conv_w_l, conv_b_l, pxc);
        // dbc = xc @ xproj^T  (4096 x 160, K=1024)
        gemm3t<<<dim3((160 + 63) / 64, ML / 128), 128>>>(pxc, xproj_l, nullptr, pdbc,
                                                         ML, 160, D_INNER, D_INNER, 0);
        // dt = softplus(dbc[:, :32] @ dtproj^T + b)  (4096 x 1024, K=32, lda=160)
        gemm3t<<<dim3(D_INNER / 64, ML / 128), 128>>>(pdbc, dtw_l, dtb_l, pdt,
                                                      ML, D_INNER, DT_RANK, 160, 1);
        // selective scan + Dp skip + silu(z) gating -> y
        scan_kernel<<<(B_ * D_INNER) / 4, 128>>>(pdt, pxc, pdbc, pxz, Alog_l, Dp_l, py);
        // h = y @ out_w^T  (4096 x 512, K=1024)
        gemm3t<<<dim3(D_MODEL / 64, ML / 128), 128>>>(py, out_w_l, nullptr, ph,
                                                      ML, D_MODEL, D_INNER, D_INNER, 0);
    }

    fc_kernel<<<1, 384>>>(ph, fc_w, fc_b, out);
}

// round 4
// speedup vs baseline: 1.2566x; 1.0914x over previous
#include <cuda_runtime.h>
#include <cuda_bf16.h>
#include <stdint.h>
#include <math.h>

// ---------------- model dims ----------------
#define B_ 4
#define L_ 1024
#define D_IN 128
#define D_MODEL 512
#define N_LAYERS 2
#define N_CLASSES 3
#define D_INNER 1024          // 2*D_MODEL
#define D_STATE 64
#define D_CONV 2
#define DT_RANK 32
#define ML (B_ * L_)          // 4096 rows

// ---------------- scratch (device globals; no allocation) ----------------
__device__ float g_h[ML * D_MODEL];
__device__ float g_xz[ML * 2 * D_INNER];     // xc = [:,0:1024], z = [:,1024:2048]
__device__ float g_xc[ML * D_INNER];
__device__ float g_dbc[ML * (DT_RANK + 2 * D_STATE)];
__device__ float g_dt[ML * D_INNER];
__device__ float g_y[ML * D_INNER];

__device__ __forceinline__ float softplus_f(float v) {
    return (v > 20.f) ? v : log1pf(__expf(v));
}
__device__ __forceinline__ float to_tf32(float x) {
    float r; asm("cvt.rna.tf32.f32 %0, %1;" : "=f"(r) : "f"(x)); return r;
}
__device__ __forceinline__ void mma_tf32(float* c, const float4& a, const float2& b) {
    asm volatile(
        "mma.sync.aligned.m16n8k8.row.col.f32.tf32.tf32.f32 "
        "{%0,%1,%2,%3}, {%4,%5,%6,%7}, {%8,%9}, {%0,%1,%2,%3};\n"
        : "+f"(c[0]), "+f"(c[1]), "+f"(c[2]), "+f"(c[3])
        : "r"(__float_as_uint(a.x)), "r"(__float_as_uint(a.y)),
          "r"(__float_as_uint(a.z)), "r"(__float_as_uint(a.w)),
          "r"(__float_as_uint(b.x)), "r"(__float_as_uint(b.y)));
}
__device__ __forceinline__ void cp16(unsigned int smem, const float* gmem, int srcbytes) {
    asm volatile("cp.async.cg.shared.global [%0], [%1], 16, %2;\n"
                 :: "r"(smem), "l"(gmem), "r"(srcbytes));
}

// ---------------- 3xTF32 tensor-core GEMM: C = A(M,K;lda) @ W(N,K)^T (+bias)(+act)
// CTA 128x128, BK=16, 256 threads = 8 warps of 64x32, cp.async double buffer.
// SMEM [row][k] stride 20 -> fragment LDS bank pattern (g*20+l4)%32 is a permutation.
#define SKS 20

__global__ __launch_bounds__(256, 2)
void gemm3t(const float* __restrict__ A, const float* __restrict__ W,
            const float* __restrict__ bias, float* __restrict__ C,
            int M, int N, int K, int lda, int act)
{
    __shared__ float As[2][128][SKS];
    __shared__ float Ws[2][128][SKS];

    const int tid = threadIdx.x;
    const int lane = tid & 31, w = tid >> 5;
    const int g = lane >> 2, l4 = lane & 3;
    const int wm = (w >> 2) * 64, wn = (w & 3) * 32;
    const int m0 = blockIdx.y * 128, n0 = blockIdx.x * 128;

    // loader mapping: row = tid/2, two float4s at col (tid%2)*8 + {0,4}
    const int lrow = tid >> 1;
    const int lcol = (tid & 1) * 8;
    const float* Ag = A + (long)(m0 + lrow) * lda + lcol;
    const int wrow = n0 + lrow;
    const float* Wg = W + (long)(wrow < N ? wrow : 0) * K + lcol;
    const int wbytes = (wrow < N) ? 16 : 0;

    const unsigned int sA0 = (unsigned int)__cvta_generic_to_shared(&As[0][lrow][lcol]);
    const unsigned int sW0 = (unsigned int)__cvta_generic_to_shared(&Ws[0][lrow][lcol]);
    const unsigned int stage = (unsigned int)(sizeof(float) * 128 * SKS);

    float acc[4][4][4];
#pragma unroll
    for (int i = 0; i < 4; i++)
#pragma unroll
        for (int j = 0; j < 4; j++)
#pragma unroll
            for (int e = 0; e < 4; e++) acc[i][j][e] = 0.f;

    const int niter = K / 16;

    // prefetch stage 0
    {
        cp16(sA0,       Ag,     16);
        cp16(sA0 + 16,  Ag + 4, 16);
        cp16(sW0,       Wg,     wbytes);
        cp16(sW0 + 16,  Wg + 4, wbytes);
        asm volatile("cp.async.commit_group;\n");
    }

    int buf = 0;
    for (int it = 0; it < niter; it++) {
        if (it + 1 < niter) {
            const int k0 = (it + 1) * 16;
            const unsigned int a = sA0 + (buf ^ 1) * stage;
            const unsigned int ww = sW0 + (buf ^ 1) * stage;
            cp16(a,       Ag + k0,     16);
            cp16(a + 16,  Ag + k0 + 4, 16);
            cp16(ww,      Wg + k0,     wbytes);
            cp16(ww + 16, Wg + k0 + 4, wbytes);
            asm volatile("cp.async.commit_group;\n");
            asm volatile("cp.async.wait_group 1;\n");
        } else {
            asm volatile("cp.async.wait_group 0;\n");
        }
        __syncthreads();

#pragma unroll
        for (int ks = 0; ks < 2; ks++) {
            const int kk = ks * 8 + l4;
            float bh[8], bl[8];
#pragma unroll
            for (int j = 0; j < 4; j++) {
                float b0 = Ws[buf][wn + 8 * j + g][kk];
                float b1 = Ws[buf][wn + 8 * j + g][kk + 4];
                bh[2 * j]     = to_tf32(b0); bl[2 * j]     = b0 - bh[2 * j];
                bh[2 * j + 1] = to_tf32(b1); bl[2 * j + 1] = b1 - bh[2 * j + 1];
            }
#pragma unroll
            for (int i = 0; i < 4; i++) {
                const int mr = wm + 16 * i + g;
                float a0 = As[buf][mr][kk];
                float a1 = As[buf][mr + 8][kk];
                float a2 = As[buf][mr][kk + 4];
                float a3 = As[buf][mr + 8][kk + 4];
                float4 ah = make_float4(to_tf32(a0), to_tf32(a1), to_tf32(a2), to_tf32(a3));
                float4 al = make_float4(a0 - ah.x, a1 - ah.y, a2 - ah.z, a3 - ah.w);
#pragma unroll
                for (int j = 0; j < 4; j++)
                    mma_tf32(acc[i][j], ah, make_float2(bh[2 * j], bh[2 * j + 1]));
#pragma unroll
                for (int j = 0; j < 4; j++)
                    mma_tf32(acc[i][j], ah, make_float2(bl[2 * j], bl[2 * j + 1]));
#pragma unroll
                for (int j = 0; j < 4; j++)
                    mma_tf32(acc[i][j], al, make_float2(bh[2 * j], bh[2 * j + 1]));
            }
        }
        __syncthreads();
        buf ^= 1;
    }

    // epilogue
#pragma unroll
    for (int i = 0; i < 4; i++) {
        const int mr0 = m0 + wm + 16 * i + g;
        const int mr1 = mr0 + 8;
#pragma unroll
        for (int j = 0; j < 4; j++) {
            const int n = n0 + wn + 8 * j + 2 * l4;
            if (n < N) {
                float b0 = 0.f, b1 = 0.f;
                if (bias) { b0 = bias[n]; b1 = bias[n + 1]; }
                float v0 = acc[i][j][0] + b0, v1 = acc[i][j][1] + b1;
                float v2 = acc[i][j][2] + b0, v3 = acc[i][j][3] + b1;
                if (act == 1) {
                    v0 = softplus_f(v0); v1 = softplus_f(v1);
                    v2 = softplus_f(v2); v3 = softplus_f(v3);
                }
                *(float2*)(C + (long)mr0 * N + n) = make_float2(v0, v1);
                *(float2*)(C + (long)mr1 * N + n) = make_float2(v2, v3);
            }
        }
    }
}

// ---------------- conv (D_CONV=2) + silu ----------------
__global__ void conv_silu_kernel(const float* __restrict__ xz,
                                 const float* __restrict__ cw,
                                 const float* __restrict__ cb,
                                 float* __restrict__ xc)
{
    int idx = blockIdx.x * blockDim.x + threadIdx.x;
    if (idx >= ML * D_INNER) return;
    int d = idx & (D_INNER - 1);
    int row = idx >> 10;
    int tt = row & (L_ - 1);
    float cur = xz[(long)row * (2 * D_INNER) + d];
    float prev = (tt > 0) ? xz[(long)(row - 1) * (2 * D_INNER) + d] : 0.f;
    float v = prev * cw[d * 2 + 0] + cur * cw[d * 2 + 1] + cb[d];
    xc[idx] = v / (1.f + __expf(-v));
}

// ---------------- selective scan: one warp per (b, d), 2 states per lane ----------
__global__ __launch_bounds__(128)
void scan_kernel(const float* __restrict__ dt, const float* __restrict__ xc,
                 const float* __restrict__ dbc, const float* __restrict__ xz,
                 const float* __restrict__ A_log, const float* __restrict__ Dp,
                 float* __restrict__ y)
{
    const int gw = (blockIdx.x * blockDim.x + threadIdx.x) >> 5;
    const int lane = threadIdx.x & 31;
    const int b = gw >> 10;
    const int d = gw & (D_INNER - 1);

    const float A0 = -__expf(A_log[d * D_STATE + 2 * lane]);
    const float A1 = -__expf(A_log[d * D_STATE + 2 * lane + 1]);
    const float Dd = Dp[d];

    const float* dtp = dt + (long)b * L_ * D_INNER + d;
    const float* xp  = xc + (long)b * L_ * D_INNER + d;
    const float* bcp = dbc + (long)b * L_ * 160 + DT_RANK + 2 * lane;
    const float* zp  = xz + (long)b * L_ * (2 * D_INNER) + D_INNER + d;
    float* yp        = y  + (long)b * L_ * D_INNER + d;

    float h0 = 0.f, h1 = 0.f;
    for (int t = 0; t < L_; t++) {
        const float dtv = dtp[t * D_INNER];
        const float xv  = xp[t * D_INNER];
        const float2 Bv = *(const float2*)(bcp + t * 160);
        const float2 Cv = *(const float2*)(bcp + t * 160 + D_STATE);
        const float u = dtv * xv;
        h0 = h0 * __expf(dtv * A0) + u * Bv.x;
        h1 = h1 * __expf(dtv * A1) + u * Bv.y;
        float p = h0 * Cv.x + h1 * Cv.y;
#pragma unroll
        for (int o = 16; o; o >>= 1) p += __shfl_xor_sync(0xffffffffu, p, o);
        if (lane == 0) {
            const float zv = zp[t * (2 * D_INNER)];
            const float yv = p + xv * Dd;
            yp[t * D_INNER] = yv * (zv / (1.f + __expf(-zv)));
        }
    }
}

// ---------------- final FC ----------------
__global__ void fc_kernel(const float* __restrict__ h, const float* __restrict__ fc_w,
                          const float* __restrict__ fc_b, float* __restrict__ out)
{
    const int w = threadIdx.x >> 5;
    const int lane = threadIdx.x & 31;
    if (w >= B_ * N_CLASSES) return;
    const int b = w / N_CLASSES, c = w % N_CLASSES;
    const float* hp = h + (long)(b * L_ + (L_ - 1)) * D_MODEL;
    float s = 0.f;
    for (int k = lane; k < D_MODEL; k += 32) s += hp[k] * fc_w[c * D_MODEL + k];
#pragma unroll
    for (int o = 16; o; o >>= 1) s += __shfl_xor_sync(0xffffffffu, s, o);
    if (lane == 0) out[b * N_CLASSES + c] = s + fc_b[c];
}

// ---------------- launch ----------------
extern "C" void kernel_launch(void* const* d_in, const int* in_sizes, int n_in,
                              void* d_out, int out_size)
{
    const float* x        = (const float*)d_in[0];
    const float* exp_w    = (const float*)d_in[1];
    const float* exp_b    = (const float*)d_in[2];
    const float* in_w     = (const float*)d_in[3];
    const float* conv_w   = (const float*)d_in[4];
    const float* conv_b   = (const float*)d_in[5];
    const float* xproj_w  = (const float*)d_in[6];
    const float* dtproj_w = (const float*)d_in[7];
    const float* dtproj_b = (const float*)d_in[8];
    const float* A_log    = (const float*)d_in[9];
    const float* Dp       = (const float*)d_in[10];
    const float* out_w    = (const float*)d_in[11];
    const float* fc_w     = (const float*)d_in[12];
    const float* fc_b     = (const float*)d_in[13];
    float* out = (float*)d_out;

    float *ph, *pxz, *pxc, *pdbc, *pdt, *py;
    cudaGetSymbolAddress((void**)&ph,   g_h);
    cudaGetSymbolAddress((void**)&pxz,  g_xz);
    cudaGetSymbolAddress((void**)&pxc,  g_xc);
    cudaGetSymbolAddress((void**)&pdbc, g_dbc);
    cudaGetSymbolAddress((void**)&pdt,  g_dt);
    cudaGetSymbolAddress((void**)&py,   g_y);

    // embed: h = x @ exp_w^T + exp_b   (4096 x 512, K=128)
    gemm3t<<<dim3(D_MODEL / 128, ML / 128), 256>>>(x, exp_w, exp_b, ph,
                                                   ML, D_MODEL, D_IN, D_IN, 0);

    for (int l = 0; l < N_LAYERS; l++) {
        const float* in_w_l   = in_w     + (long)l * 2 * D_INNER * D_MODEL;
        const float* conv_w_l = conv_w   + (long)l * D_INNER * D_CONV;
        const float* conv_b_l = conv_b   + (long)l * D_INNER;
        const float* xproj_l  = xproj_w  + (long)l * 160 * D_INNER;
        const float* dtw_l    = dtproj_w + (long)l * D_INNER * DT_RANK;
        const float* dtb_l    = dtproj_b + (long)l * D_INNER;
        const float* Alog_l   = A_log    + (long)l * D_INNER * D_STATE;
        const float* Dp_l     = Dp       + (long)l * D_INNER;
        const float* out_w_l  = out_w    + (long)l * D_MODEL * D_INNER;

        // xz = h @ in_w^T   (4096 x 2048, K=512)
        gemm3t<<<dim3(2 * D_INNER / 128, ML / 128), 256>>>(ph, in_w_l, nullptr, pxz,
                                                           ML, 2 * D_INNER, D_MODEL, D_MODEL, 0);
        // conv + silu
        conv_silu_kernel<<<(ML * D_INNER + 255) / 256, 256>>>(pxz, conv_w_l, conv_b_l, pxc);
        // dbc = xc @ xproj^T  (4096 x 160, K=1024)
        gemm3t<<<dim3((160 + 127) / 128, ML / 128), 256>>>(pxc, xproj_l, nullptr, pdbc,
                                                           ML, 160, D_INNER, D_INNER, 0);
        // dt = softplus(dbc[:, :32] @ dtproj^T + b)  (4096 x 1024, K=32, lda=160)
        gemm3t<<<dim3(D_INNER / 128, ML / 128), 256>>>(pdbc, dtw_l, dtb_l, pdt,
                                                       ML, D_INNER, DT_RANK, 160, 1);
        // selective scan + Dp skip + silu(z) gating -> y
        scan_kernel<<<(B_ * D_INNER) / 4, 128>>>(pdt, pxc, pdbc, pxz, Alog_l, Dp_l, py);
        // h = y @ out_w^T  (4096 x 512, K=1024)
        gemm3t<<<dim3(D_MODEL / 128, ML / 128), 256>>>(py, out_w_l, nullptr, ph,
                                                       ML, D_MODEL, D_INNER, D_INNER, 0);
    }

    fc_kernel<<<1, 384>>>(ph, fc_w, fc_b, out);
}

// round 5
// speedup vs baseline: 1.2848x; 1.0225x over previous
#include <cuda_runtime.h>
#include <cuda_bf16.h>
#include <stdint.h>
#include <math.h>

// ---------------- model dims ----------------
#define B_ 4
#define L_ 1024
#define D_IN 128
#define D_MODEL 512
#define N_LAYERS 2
#define N_CLASSES 3
#define D_INNER 1024          // 2*D_MODEL
#define D_STATE 64
#define D_CONV 2
#define DT_RANK 32
#define ML (B_ * L_)          // 4096 rows

// ---------------- scratch (device globals; no allocation) ----------------
__device__ float g_h[ML * D_MODEL];
__device__ float g_xz[ML * 2 * D_INNER];     // xc = [:,0:1024], z = [:,1024:2048]
__device__ float g_xc[ML * D_INNER];
__device__ float g_dbc[ML * (DT_RANK + 2 * D_STATE)];
__device__ float g_dt[ML * D_INNER];
__device__ float g_y[ML * D_INNER];

__device__ __forceinline__ float softplus_f(float v) {
    return (v > 20.f) ? v : log1pf(__expf(v));
}

// split a float pair into bf16x2 hi word + bf16x2 lo (residual) word
__device__ __forceinline__ void split2(float e0, float e1, unsigned int& hi, unsigned int& lo) {
    __nv_bfloat162 h = __floats2bfloat162_rn(e0, e1);
    float r0 = e0 - __bfloat162float(h.x);
    float r1 = e1 - __bfloat162float(h.y);
    __nv_bfloat162 l = __floats2bfloat162_rn(r0, r1);
    hi = *reinterpret_cast<unsigned int*>(&h);
    lo = *reinterpret_cast<unsigned int*>(&l);
}

__device__ __forceinline__ void mma_bf16(float* c, const unsigned int* a, const unsigned int* b) {
    asm volatile(
        "mma.sync.aligned.m16n8k16.row.col.f32.bf16.bf16.f32 "
        "{%0,%1,%2,%3}, {%4,%5,%6,%7}, {%8,%9}, {%0,%1,%2,%3};\n"
        : "+f"(c[0]), "+f"(c[1]), "+f"(c[2]), "+f"(c[3])
        : "r"(a[0]), "r"(a[1]), "r"(a[2]), "r"(a[3]),
          "r"(b[0]), "r"(b[1]));
}

// ---------------- split-bf16 (3-term) GEMM: C = A(M,K;lda) @ W(N,K)^T (+bias)(+act)
// CTA 128x128, BK=32, 256 threads = 8 warps of 64x32.
// SMEM words are bf16x2 k-pairs; row stride 20 words -> conflict-free fragment LDS.
#define SKW 20   // 16 pair-words + 4 pad

__global__ __launch_bounds__(256, 2)
void gemm3b(const float* __restrict__ A, const float* __restrict__ W,
            const float* __restrict__ bias, float* __restrict__ C,
            int M, int N, int K, int lda, int act)
{
    // [stage][array: 0=Ah 1=Al 2=Wh 3=Wl][row][pair-word]
    __shared__ unsigned int SH[2][4][128][SKW];

    const int tid = threadIdx.x;
    const int lane = tid & 31, w = tid >> 5;
    const int g = lane >> 2, l4 = lane & 3;
    const int wm = (w >> 2) * 64, wn = (w & 3) * 32;
    const int m0 = blockIdx.y * 128, n0 = blockIdx.x * 128;

    // loader: row = tid/2, float col base = (tid%2)*16, 4 float4s per tile
    const int lrow = tid >> 1;
    const int lcolf = (tid & 1) * 16;
    const int p0 = lcolf >> 1;                 // first pair-word index (0 or 8)
    const float* Ag = A + (long)(m0 + lrow) * lda + lcolf;
    const int wrow = n0 + lrow;
    const float* Wg = W + (long)(wrow < N ? wrow : 0) * K + lcolf;

    float4 ra[4], rw[4];

    float acc[4][4][4];
#pragma unroll
    for (int i = 0; i < 4; i++)
#pragma unroll
        for (int j = 0; j < 4; j++)
#pragma unroll
            for (int e = 0; e < 4; e++) acc[i][j][e] = 0.f;

    const int niter = K / 32;

    // prologue: load + stage tile 0
#pragma unroll
    for (int q = 0; q < 4; q++) {
        ra[q] = *(const float4*)(Ag + q * 4);
        rw[q] = *(const float4*)(Wg + q * 4);
    }
#pragma unroll
    for (int q = 0; q < 4; q++) {
        unsigned int h0, l0, h1, l1;
        split2(ra[q].x, ra[q].y, h0, l0);
        split2(ra[q].z, ra[q].w, h1, l1);
        SH[0][0][lrow][p0 + 2*q]     = h0;
        SH[0][0][lrow][p0 + 2*q + 1] = h1;
        SH[0][1][lrow][p0 + 2*q]     = l0;
        SH[0][1][lrow][p0 + 2*q + 1] = l1;
        split2(rw[q].x, rw[q].y, h0, l0);
        split2(rw[q].z, rw[q].w, h1, l1);
        SH[0][2][lrow][p0 + 2*q]     = h0;
        SH[0][2][lrow][p0 + 2*q + 1] = h1;
        SH[0][3][lrow][p0 + 2*q]     = l0;
        SH[0][3][lrow][p0 + 2*q + 1] = l1;
    }
    __syncthreads();

    for (int it = 0; it < niter; it++) {
        const int s = it & 1;
        if (it + 1 < niter) {
            const int k0 = (it + 1) * 32;
#pragma unroll
            for (int q = 0; q < 4; q++) {
                ra[q] = *(const float4*)(Ag + k0 + q * 4);
                rw[q] = *(const float4*)(Wg + k0 + q * 4);
            }
        }

#pragma unroll
        for (int ks = 0; ks < 2; ks++) {
            const int kb = ks * 8 + l4;
            unsigned int bh[4][2], bl[4][2];
#pragma unroll
            for (int j = 0; j < 4; j++) {
                const int r = wn + 8 * j + g;
                bh[j][0] = SH[s][2][r][kb];
                bh[j][1] = SH[s][2][r][kb + 4];
                bl[j][0] = SH[s][3][r][kb];
                bl[j][1] = SH[s][3][r][kb + 4];
            }
#pragma unroll
            for (int i = 0; i < 4; i++) {
                const int r0 = wm + 16 * i + g, r1 = r0 + 8;
                unsigned int ah[4], al[4];
                ah[0] = SH[s][0][r0][kb];     ah[1] = SH[s][0][r1][kb];
                ah[2] = SH[s][0][r0][kb + 4]; ah[3] = SH[s][0][r1][kb + 4];
                al[0] = SH[s][1][r0][kb];     al[1] = SH[s][1][r1][kb];
                al[2] = SH[s][1][r0][kb + 4]; al[3] = SH[s][1][r1][kb + 4];
#pragma unroll
                for (int j = 0; j < 4; j++) mma_bf16(acc[i][j], ah, bh[j]);
#pragma unroll
                for (int j = 0; j < 4; j++) mma_bf16(acc[i][j], ah, bl[j]);
#pragma unroll
                for (int j = 0; j < 4; j++) mma_bf16(acc[i][j], al, bh[j]);
            }
        }

        if (it + 1 < niter) {
            const int s2 = (it + 1) & 1;
#pragma unroll
            for (int q = 0; q < 4; q++) {
                unsigned int h0, l0, h1, l1;
                split2(ra[q].x, ra[q].y, h0, l0);
                split2(ra[q].z, ra[q].w, h1, l1);
                SH[s2][0][lrow][p0 + 2*q]     = h0;
                SH[s2][0][lrow][p0 + 2*q + 1] = h1;
                SH[s2][1][lrow][p0 + 2*q]     = l0;
                SH[s2][1][lrow][p0 + 2*q + 1] = l1;
                split2(rw[q].x, rw[q].y, h0, l0);
                split2(rw[q].z, rw[q].w, h1, l1);
                SH[s2][2][lrow][p0 + 2*q]     = h0;
                SH[s2][2][lrow][p0 + 2*q + 1] = h1;
                SH[s2][3][lrow][p0 + 2*q]     = l0;
                SH[s2][3][lrow][p0 + 2*q + 1] = l1;
            }
        }
        __syncthreads();
    }

    // epilogue (c-fragment: rows g / g+8, cols 2*l4, 2*l4+1)
#pragma unroll
    for (int i = 0; i < 4; i++) {
        const int mr0 = m0 + wm + 16 * i + g;
        const int mr1 = mr0 + 8;
#pragma unroll
        for (int j = 0; j < 4; j++) {
            const int n = n0 + wn + 8 * j + 2 * l4;
            if (n < N) {
                float b0 = 0.f, b1 = 0.f;
                if (bias) { b0 = bias[n]; b1 = bias[n + 1]; }
                float v0 = acc[i][j][0] + b0, v1 = acc[i][j][1] + b1;
                float v2 = acc[i][j][2] + b0, v3 = acc[i][j][3] + b1;
                if (act == 1) {
                    v0 = softplus_f(v0); v1 = softplus_f(v1);
                    v2 = softplus_f(v2); v3 = softplus_f(v3);
                }
                *(float2*)(C + (long)mr0 * N + n) = make_float2(v0, v1);
                *(float2*)(C + (long)mr1 * N + n) = make_float2(v2, v3);
            }
        }
    }
}

// ---------------- conv (D_CONV=2) + silu ----------------
__global__ void conv_silu_kernel(const float* __restrict__ xz,
                                 const float* __restrict__ cw,
                                 const float* __restrict__ cb,
                                 float* __restrict__ xc)
{
    int idx = blockIdx.x * blockDim.x + threadIdx.x;
    if (idx >= ML * D_INNER) return;
    int d = idx & (D_INNER - 1);
    int row = idx >> 10;
    int tt = row & (L_ - 1);
    float cur = xz[(long)row * (2 * D_INNER) + d];
    float prev = (tt > 0) ? xz[(long)(row - 1) * (2 * D_INNER) + d] : 0.f;
    float v = prev * cw[d * 2 + 0] + cur * cw[d * 2 + 1] + cb[d];
    xc[idx] = v / (1.f + __expf(-v));
}

// ---------------- selective scan: one warp per (b, d), 2 states per lane ----------
__global__ __launch_bounds__(128)
void scan_kernel(const float* __restrict__ dt, const float* __restrict__ xc,
                 const float* __restrict__ dbc, const float* __restrict__ xz,
                 const float* __restrict__ A_log, const float* __restrict__ Dp,
                 float* __restrict__ y)
{
    const int gw = (blockIdx.x * blockDim.x + threadIdx.x) >> 5;
    const int lane = threadIdx.x & 31;
    const int b = gw >> 10;
    const int d = gw & (D_INNER - 1);

    const float A0 = -__expf(A_log[d * D_STATE + 2 * lane]);
    const float A1 = -__expf(A_log[d * D_STATE + 2 * lane + 1]);
    const float Dd = Dp[d];

    const float* dtp = dt + (long)b * L_ * D_INNER + d;
    const float* xp  = xc + (long)b * L_ * D_INNER + d;
    const float* bcp = dbc + (long)b * L_ * 160 + DT_RANK + 2 * lane;
    const float* zp  = xz + (long)b * L_ * (2 * D_INNER) + D_INNER + d;
    float* yp        = y  + (long)b * L_ * D_INNER + d;

    float h0 = 0.f, h1 = 0.f;
    for (int t = 0; t < L_; t++) {
        const float dtv = dtp[t * D_INNER];
        const float xv  = xp[t * D_INNER];
        const float2 Bv = *(const float2*)(bcp + t * 160);
        const float2 Cv = *(const float2*)(bcp + t * 160 + D_STATE);
        const float u = dtv * xv;
        h0 = h0 * __expf(dtv * A0) + u * Bv.x;
        h1 = h1 * __expf(dtv * A1) + u * Bv.y;
        float p = h0 * Cv.x + h1 * Cv.y;
#pragma unroll
        for (int o = 16; o; o >>= 1) p += __shfl_xor_sync(0xffffffffu, p, o);
        if (lane == 0) {
            const float zv = zp[t * (2 * D_INNER)];
            const float yv = p + xv * Dd;
            yp[t * D_INNER] = yv * (zv / (1.f + __expf(-zv)));
        }
    }
}

// ---------------- final FC ----------------
__global__ void fc_kernel(const float* __restrict__ h, const float* __restrict__ fc_w,
                          const float* __restrict__ fc_b, float* __restrict__ out)
{
    const int w = threadIdx.x >> 5;
    const int lane = threadIdx.x & 31;
    if (w >= B_ * N_CLASSES) return;
    const int b = w / N_CLASSES, c = w % N_CLASSES;
    const float* hp = h + (long)(b * L_ + (L_ - 1)) * D_MODEL;
    float s = 0.f;
    for (int k = lane; k < D_MODEL; k += 32) s += hp[k] * fc_w[c * D_MODEL + k];
#pragma unroll
    for (int o = 16; o; o >>= 1) s += __shfl_xor_sync(0xffffffffu, s, o);
    if (lane == 0) out[b * N_CLASSES + c] = s + fc_b[c];
}

// ---------------- launch ----------------
extern "C" void kernel_launch(void* const* d_in, const int* in_sizes, int n_in,
                              void* d_out, int out_size)
{
    const float* x        = (const float*)d_in[0];
    const float* exp_w    = (const float*)d_in[1];
    const float* exp_b    = (const float*)d_in[2];
    const float* in_w     = (const float*)d_in[3];
    const float* conv_w   = (const float*)d_in[4];
    const float* conv_b   = (const float*)d_in[5];
    const float* xproj_w  = (const float*)d_in[6];
    const float* dtproj_w = (const float*)d_in[7];
    const float* dtproj_b = (const float*)d_in[8];
    const float* A_log    = (const float*)d_in[9];
    const float* Dp       = (const float*)d_in[10];
    const float* out_w    = (const float*)d_in[11];
    const float* fc_w     = (const float*)d_in[12];
    const float* fc_b     = (const float*)d_in[13];
    float* out = (float*)d_out;

    float *ph, *pxz, *pxc, *pdbc, *pdt, *py;
    cudaGetSymbolAddress((void**)&ph,   g_h);
    cudaGetSymbolAddress((void**)&pxz,  g_xz);
    cudaGetSymbolAddress((void**)&pxc,  g_xc);
    cudaGetSymbolAddress((void**)&pdbc, g_dbc);
    cudaGetSymbolAddress((void**)&pdt,  g_dt);
    cudaGetSymbolAddress((void**)&py,   g_y);

    // embed: h = x @ exp_w^T + exp_b   (4096 x 512, K=128)
    gemm3b<<<dim3(D_MODEL / 128, ML / 128), 256>>>(x, exp_w, exp_b, ph,
                                                   ML, D_MODEL, D_IN, D_IN, 0);

    for (int l = 0; l < N_LAYERS; l++) {
        const float* in_w_l   = in_w     + (long)l * 2 * D_INNER * D_MODEL;
        const float* conv_w_l = conv_w   + (long)l * D_INNER * D_CONV;
        const float* conv_b_l = conv_b   + (long)l * D_INNER;
        const float* xproj_l  = xproj_w  + (long)l * 160 * D_INNER;
        const float* dtw_l    = dtproj_w + (long)l * D_INNER * DT_RANK;
        const float* dtb_l    = dtproj_b + (long)l * D_INNER;
        const float* Alog_l   = A_log    + (long)l * D_INNER * D_STATE;
        const float* Dp_l     = Dp       + (long)l * D_INNER;
        const float* out_w_l  = out_w    + (long)l * D_MODEL * D_INNER;

        // xz = h @ in_w^T   (4096 x 2048, K=512)
        gemm3b<<<dim3(2 * D_INNER / 128, ML / 128), 256>>>(ph, in_w_l, nullptr, pxz,
                                                           ML, 2 * D_INNER, D_MODEL, D_MODEL, 0);
        // conv + silu
        conv_silu_kernel<<<(ML * D_INNER + 255) / 256, 256>>>(pxz, conv_w_l, conv_b_l, pxc);
        // dbc = xc @ xproj^T  (4096 x 160, K=1024)
        gemm3b<<<dim3((160 + 127) / 128, ML / 128), 256>>>(pxc, xproj_l, nullptr, pdbc,
                                                           ML, 160, D_INNER, D_INNER, 0);
        // dt = softplus(dbc[:, :32] @ dtproj^T + b)  (4096 x 1024, K=32, lda=160)
        gemm3b<<<dim3(D_INNER / 128, ML / 128), 256>>>(pdbc, dtw_l, dtb_l, pdt,
                                                       ML, D_INNER, DT_RANK, 160, 1);
        // selective scan + Dp skip + silu(z) gating -> y
        scan_kernel<<<(B_ * D_INNER) / 4, 128>>>(pdt, pxc, pdbc, pxz, Alog_l, Dp_l, py);
        // h = y @ out_w^T  (4096 x 512, K=1024)
        gemm3b<<<dim3(D_MODEL / 128, ML / 128), 256>>>(py, out_w_l, nullptr, ph,
                                                       ML, D_MODEL, D_INNER, D_INNER, 0);
    }

    fc_kernel<<<1, 384>>>(ph, fc_w, fc_b, out);
}